// round 4
// baseline (speedup 1.0000x reference)
#include <cuda_runtime.h>
#include <cuda_bf16.h>
#include <cstdint>

#define NN 100000
#define EE 1600000

typedef unsigned long long u64;

// Scratch (static device globals: allocation-free rule)
__device__ __align__(16) float g_agg1[NN * 128];
__device__ __align__(16) float g_cnt[NN];
__device__ __align__(16) float g_hl[NN * 64];
__device__ __align__(16) float g_ho[NN * 64];
__device__ __align__(16) float g_agg2[NN * 64];

__device__ __forceinline__ void red_add_v4(float* p, float4 v) {
    asm volatile("red.global.add.v4.f32 [%0], {%1,%2,%3,%4};"
                 :: "l"(p), "f"(v.x), "f"(v.y), "f"(v.z), "f"(v.w)
                 : "memory");
}
__device__ __forceinline__ u64 fma2(u64 a, u64 b, u64 c) {
    u64 d; asm("fma.rn.f32x2 %0,%1,%2,%3;" : "=l"(d) : "l"(a), "l"(b), "l"(c));
    return d;
}
__device__ __forceinline__ u64 dup2(float v) {
    u64 r; asm("mov.b64 %0,{%1,%1};" : "=l"(r) : "f"(v)); return r;
}
__device__ __forceinline__ u64 pack2(float a, float b) {
    u64 r; asm("mov.b64 %0,{%1,%2};" : "=l"(r) : "f"(a), "f"(b)); return r;
}
__device__ __forceinline__ float2 unpack2(u64 v) {
    float2 f; asm("mov.b64 {%0,%1},%2;" : "=f"(f.x), "=f"(f.y) : "l"(v)); return f;
}

// ---------------------------------------------------------------------------
// Zero scratch accumulators
// ---------------------------------------------------------------------------
__global__ void zero_kernel() {
    int tid = blockIdx.x * blockDim.x + threadIdx.x;
    int stride = gridDim.x * blockDim.x;
    float4 z = make_float4(0.f, 0.f, 0.f, 0.f);
    float4* a1 = (float4*)g_agg1;
    float4* a2 = (float4*)g_agg2;
    float4* c  = (float4*)g_cnt;
    for (int i = tid; i < NN * 128 / 4; i += stride) a1[i] = z;
    for (int i = tid; i < NN * 64 / 4;  i += stride) a2[i] = z;
    for (int i = tid; i < NN / 4;       i += stride) c[i]  = z;
}

// ---------------------------------------------------------------------------
// Layer-1 edge scatter: agg1[dst] += x[src] (128 f32/edge, 1 warp/edge) + degree
// ---------------------------------------------------------------------------
__global__ void scatter1_kernel(const float* __restrict__ x,
                                const int* __restrict__ ei) {
    int gw   = (blockIdx.x * blockDim.x + threadIdx.x) >> 5;
    int lane = threadIdx.x & 31;
    int nw   = (gridDim.x * blockDim.x) >> 5;
    for (int e = gw; e < EE; e += nw) {
        int s = ei[e];
        int d = ei[EE + e];
        float4 v = ((const float4*)(x + (size_t)s * 128))[lane];
        red_add_v4(g_agg1 + (size_t)d * 128 + lane * 4, v);
        if (lane == 0) atomicAdd(g_cnt + d, 1.0f);
    }
}

// ---------------------------------------------------------------------------
// Layer-2 edge scatter: agg2[dst] += hl[src] (64 f32/edge, half-warp/edge)
// ---------------------------------------------------------------------------
__global__ void scatter2_kernel(const int* __restrict__ ei) {
    int tid = blockIdx.x * blockDim.x + threadIdx.x;
    int hw  = tid >> 4;
    int l   = tid & 15;
    int nhw = (gridDim.x * blockDim.x) >> 4;
    for (int e = hw; e < EE; e += nhw) {
        int s = ei[e];
        int d = ei[EE + e];
        float4 v = ((const float4*)(g_hl + (size_t)s * 64))[l];
        red_add_v4(g_agg2 + (size_t)d * 64 + l * 4, v);
    }
}

// ---------------------------------------------------------------------------
// Fused GEMM kernel:
//   h  = relu(BN(mean@W1l^T + b1l + x@W1r^T))        (kept in smem only)
//   hl = h @ W2l^T            -> g_hl  (feeds scatter2)
//   ho = h @ W2r^T + b2l      -> g_ho  (feeds out_add)
// Weights in smem (192 KB): WTl[k][128], WTr[k][128], W2c[k][128]
// (W2c cols 0-63 = W2l^T, 64-127 = W2r^T). 4 warps/block, 8 nodes/warp-task.
// f32x2 packed FMAs; lane owns 4 output channels = 2 f32 pairs.
// ---------------------------------------------------------------------------
__global__ __launch_bounds__(128, 1)
void fused_kernel(const float* __restrict__ x,
                  const float* __restrict__ W1l,
                  const float* __restrict__ b1l,
                  const float* __restrict__ W1r,
                  const float* __restrict__ gamma,
                  const float* __restrict__ beta,
                  const float* __restrict__ rmean,
                  const float* __restrict__ rvar,
                  const float* __restrict__ W2l,
                  const float* __restrict__ b2l,
                  const float* __restrict__ W2r) {
    extern __shared__ float sm[];
    float* WTl = sm;             // 16384 floats
    float* WTr = sm + 16384;     // 16384
    float* W2c = sm + 32768;     // 16384
    float* buf = sm + 49152;     // 4 warps * 2048 floats

    for (int i = threadIdx.x; i < 16384; i += blockDim.x) {
        int k = i >> 7, j = i & 127;
        WTl[i] = W1l[j * 128 + k];
        WTr[i] = W1r[j * 128 + k];
        W2c[i] = (j < 64) ? W2l[j * 128 + k] : W2r[(j - 64) * 128 + k];
    }
    __syncthreads();

    int wid = threadIdx.x >> 5, lane = threadIdx.x & 31;
    float* mb = buf + wid * 2048;   // [8][128]  (mean, later h)
    float* xb = mb + 1024;          // [8][128]  (x)

    // BN constants for lane's 4 channels c = 4*lane .. 4*lane+3
    float4 g4  = ((const float4*)gamma)[lane];
    float4 be4 = ((const float4*)beta)[lane];
    float4 rm4 = ((const float4*)rmean)[lane];
    float4 rv4 = ((const float4*)rvar)[lane];
    float4 bl4 = ((const float4*)b1l)[lane];
    float sx = g4.x * rsqrtf(rv4.x + 1e-5f);
    float sy = g4.y * rsqrtf(rv4.y + 1e-5f);
    float sz = g4.z * rsqrtf(rv4.z + 1e-5f);
    float sw = g4.w * rsqrtf(rv4.w + 1e-5f);
    u64 sc01 = pack2(sx, sy), sc23 = pack2(sz, sw);
    u64 sh01 = pack2((bl4.x - rm4.x) * sx + be4.x, (bl4.y - rm4.y) * sy + be4.y);
    u64 sh23 = pack2((bl4.z - rm4.z) * sz + be4.z, (bl4.w - rm4.w) * sw + be4.w);

    float4 b2v = make_float4(0.f, 0.f, 0.f, 0.f);
    if (lane >= 16) b2v = ((const float4*)b2l)[lane - 16];

    int gw = blockIdx.x * 4 + wid;
    int nw = gridDim.x * 4;
    const int NTASK = NN / 8;   // 12500

    for (int t = gw; t < NTASK; t += nw) {
        int base = t * 8;
        // ---- stage x rows and mean rows into per-warp smem ----
        #pragma unroll
        for (int m = 0; m < 8; m++) {
            int node = base + m;
            ((float4*)(xb + m * 128))[lane] =
                ((const float4*)(x + (size_t)node * 128))[lane];
            float inv = 1.0f / fmaxf(g_cnt[node], 1.0f);
            float4 a = ((const float4*)(g_agg1 + (size_t)node * 128))[lane];
            a.x *= inv; a.y *= inv; a.z *= inv; a.w *= inv;
            ((float4*)(mb + m * 128))[lane] = a;
        }
        __syncwarp();

        // ---- phase 1: acc = mean@W1l^T + x@W1r^T ----
        u64 acc0[8], acc1[8];
        #pragma unroll
        for (int m = 0; m < 8; m++) { acc0[m] = 0ull; acc1[m] = 0ull; }

        for (int k0 = 0; k0 < 128; k0 += 4) {
            float4 s[8];
            // pass A: mean * W1l
            #pragma unroll
            for (int m = 0; m < 8; m++) s[m] = *(const float4*)(mb + m * 128 + k0);
            #pragma unroll
            for (int kk = 0; kk < 4; kk++) {
                ulonglong2 w = ((const ulonglong2*)(WTl + (k0 + kk) * 128))[lane];
                #pragma unroll
                for (int m = 0; m < 8; m++) {
                    float v = (kk == 0) ? s[m].x : (kk == 1) ? s[m].y
                             : (kk == 2) ? s[m].z : s[m].w;
                    u64 d = dup2(v);
                    acc0[m] = fma2(d, w.x, acc0[m]);
                    acc1[m] = fma2(d, w.y, acc1[m]);
                }
            }
            // pass B: x * W1r
            #pragma unroll
            for (int m = 0; m < 8; m++) s[m] = *(const float4*)(xb + m * 128 + k0);
            #pragma unroll
            for (int kk = 0; kk < 4; kk++) {
                ulonglong2 w = ((const ulonglong2*)(WTr + (k0 + kk) * 128))[lane];
                #pragma unroll
                for (int m = 0; m < 8; m++) {
                    float v = (kk == 0) ? s[m].x : (kk == 1) ? s[m].y
                             : (kk == 2) ? s[m].z : s[m].w;
                    u64 d = dup2(v);
                    acc0[m] = fma2(d, w.x, acc0[m]);
                    acc1[m] = fma2(d, w.y, acc1[m]);
                }
            }
        }

        // ---- epilogue 1: BN + ReLU, write h into mb ----
        __syncwarp();
        #pragma unroll
        for (int m = 0; m < 8; m++) {
            u64 h01 = fma2(acc0[m], sc01, sh01);
            u64 h23 = fma2(acc1[m], sc23, sh23);
            float2 a = unpack2(h01), b = unpack2(h23);
            float4 h4;
            h4.x = fmaxf(a.x, 0.f); h4.y = fmaxf(a.y, 0.f);
            h4.z = fmaxf(b.x, 0.f); h4.w = fmaxf(b.y, 0.f);
            ((float4*)(mb + m * 128))[lane] = h4;
        }
        __syncwarp();

        // ---- phase 2: [hl|ho] = h @ W2c ----
        u64 p0[8], p1[8];
        #pragma unroll
        for (int m = 0; m < 8; m++) { p0[m] = 0ull; p1[m] = 0ull; }

        for (int k0 = 0; k0 < 128; k0 += 4) {
            float4 s[8];
            #pragma unroll
            for (int m = 0; m < 8; m++) s[m] = *(const float4*)(mb + m * 128 + k0);
            #pragma unroll
            for (int kk = 0; kk < 4; kk++) {
                ulonglong2 w = ((const ulonglong2*)(W2c + (k0 + kk) * 128))[lane];
                #pragma unroll
                for (int m = 0; m < 8; m++) {
                    float v = (kk == 0) ? s[m].x : (kk == 1) ? s[m].y
                             : (kk == 2) ? s[m].z : s[m].w;
                    u64 d = dup2(v);
                    p0[m] = fma2(d, w.x, p0[m]);
                    p1[m] = fma2(d, w.y, p1[m]);
                }
            }
        }

        // ---- epilogue 2: lanes 0-15 -> hl, lanes 16-31 -> ho (+b2) ----
        #pragma unroll
        for (int m = 0; m < 8; m++) {
            float2 a = unpack2(p0[m]), b = unpack2(p1[m]);
            int node = base + m;
            if (lane < 16) {
                float4 v = make_float4(a.x, a.y, b.x, b.y);
                ((float4*)(g_hl + (size_t)node * 64))[lane] = v;
            } else {
                float4 v = make_float4(a.x + b2v.x, a.y + b2v.y,
                                       b.x + b2v.z, b.y + b2v.w);
                ((float4*)(g_ho + (size_t)node * 64))[lane - 16] = v;
            }
        }
        __syncwarp();
    }
}

// ---------------------------------------------------------------------------
// out = ho + agg2 / cnt   (elementwise, float4 granularity)
// ---------------------------------------------------------------------------
__global__ void out_add_kernel(float* __restrict__ out) {
    int tid = blockIdx.x * blockDim.x + threadIdx.x;
    int stride = gridDim.x * blockDim.x;
    const float4* ho4 = (const float4*)g_ho;
    const float4* a4  = (const float4*)g_agg2;
    float4* o4 = (float4*)out;
    for (int i = tid; i < NN * 16; i += stride) {   // 16 float4 per node row
        int node = i >> 4;
        float inv = 1.0f / fmaxf(g_cnt[node], 1.0f);
        float4 h = ho4[i];
        float4 a = a4[i];
        h.x += a.x * inv; h.y += a.y * inv;
        h.z += a.z * inv; h.w += a.w * inv;
        o4[i] = h;
    }
}

// ---------------------------------------------------------------------------
extern "C" void kernel_launch(void* const* d_in, const int* in_sizes, int n_in,
                              void* d_out, int out_size) {
    const float* x     = (const float*)d_in[0];
    const int*   ei    = (const int*)d_in[1];
    const float* W1l   = (const float*)d_in[2];
    const float* b1l   = (const float*)d_in[3];
    const float* W1r   = (const float*)d_in[4];
    const float* gamma = (const float*)d_in[5];
    const float* beta  = (const float*)d_in[6];
    const float* rmean = (const float*)d_in[7];
    const float* rvar  = (const float*)d_in[8];
    const float* W2l   = (const float*)d_in[9];
    const float* b2l   = (const float*)d_in[10];
    const float* W2r   = (const float*)d_in[11];
    float* out = (float*)d_out;

    const int SMEMF = (49152 + 4 * 2048) * 4;   // 229376 B
    cudaFuncSetAttribute(fused_kernel, cudaFuncAttributeMaxDynamicSharedMemorySize, SMEMF);

    zero_kernel<<<1024, 256>>>();
    scatter1_kernel<<<8192, 256>>>(x, ei);
    fused_kernel<<<152, 128, SMEMF>>>(x, W1l, b1l, W1r, gamma, beta, rmean,
                                      rvar, W2l, b2l, W2r);
    scatter2_kernel<<<8192, 256>>>(ei);
    out_add_kernel<<<2048, 256>>>(out);
}

// round 5
// speedup vs baseline: 1.0447x; 1.0447x over previous
#include <cuda_runtime.h>
#include <cuda_bf16.h>
#include <cstdint>

#define NN 100000
#define EE 1600000

typedef unsigned long long u64;

// Scratch (static device globals: allocation-free rule)
__device__ __align__(16) float g_agg1[NN * 128];
__device__ __align__(16) float g_cnt[NN];
__device__ __align__(16) float g_hl[NN * 64];
__device__ __align__(16) float g_ho[NN * 64];
__device__ __align__(16) float g_agg2[NN * 64];

__device__ __forceinline__ void red_add_v4(float* p, float4 v) {
    asm volatile("red.global.add.v4.f32 [%0], {%1,%2,%3,%4};"
                 :: "l"(p), "f"(v.x), "f"(v.y), "f"(v.z), "f"(v.w)
                 : "memory");
}
__device__ __forceinline__ u64 fma2(u64 a, u64 b, u64 c) {
    u64 d; asm("fma.rn.f32x2 %0,%1,%2,%3;" : "=l"(d) : "l"(a), "l"(b), "l"(c));
    return d;
}
__device__ __forceinline__ u64 dup2(float v) {
    u64 r; asm("mov.b64 %0,{%1,%1};" : "=l"(r) : "f"(v)); return r;
}
__device__ __forceinline__ u64 pack2(float a, float b) {
    u64 r; asm("mov.b64 %0,{%1,%2};" : "=l"(r) : "f"(a), "f"(b)); return r;
}
__device__ __forceinline__ float2 unpack2(u64 v) {
    float2 f; asm("mov.b64 {%0,%1},%2;" : "=f"(f.x), "=f"(f.y) : "l"(v)); return f;
}

// ---------------------------------------------------------------------------
// Zero scratch accumulators
// ---------------------------------------------------------------------------
__global__ void zero_kernel() {
    int tid = blockIdx.x * blockDim.x + threadIdx.x;
    int stride = gridDim.x * blockDim.x;
    float4 z = make_float4(0.f, 0.f, 0.f, 0.f);
    float4* a1 = (float4*)g_agg1;
    float4* a2 = (float4*)g_agg2;
    float4* c  = (float4*)g_cnt;
    for (int i = tid; i < NN * 128 / 4; i += stride) a1[i] = z;
    for (int i = tid; i < NN * 64 / 4;  i += stride) a2[i] = z;
    for (int i = tid; i < NN / 4;       i += stride) c[i]  = z;
}

// ---------------------------------------------------------------------------
// Layer-1 edge scatter: agg1[dst] += x[src] (128 f32/edge, 1 warp/edge) + degree
// ---------------------------------------------------------------------------
__global__ void scatter1_kernel(const float* __restrict__ x,
                                const int* __restrict__ ei) {
    int gw   = (blockIdx.x * blockDim.x + threadIdx.x) >> 5;
    int lane = threadIdx.x & 31;
    int nw   = (gridDim.x * blockDim.x) >> 5;
    for (int e = gw; e < EE; e += nw) {
        int s = ei[e];
        int d = ei[EE + e];
        float4 v = ((const float4*)(x + (size_t)s * 128))[lane];
        red_add_v4(g_agg1 + (size_t)d * 128 + lane * 4, v);
        if (lane == 0) atomicAdd(g_cnt + d, 1.0f);
    }
}

// ---------------------------------------------------------------------------
// Layer-2 edge scatter: agg2[dst] += hl[src] (64 f32/edge, half-warp/edge)
// ---------------------------------------------------------------------------
__global__ void scatter2_kernel(const int* __restrict__ ei) {
    int tid = blockIdx.x * blockDim.x + threadIdx.x;
    int hw  = tid >> 4;
    int l   = tid & 15;
    int nhw = (gridDim.x * blockDim.x) >> 4;
    for (int e = hw; e < EE; e += nhw) {
        int s = ei[e];
        int d = ei[EE + e];
        float4 v = ((const float4*)(g_hl + (size_t)s * 64))[l];
        red_add_v4(g_agg2 + (size_t)d * 64 + l * 4, v);
    }
}

// ---------------------------------------------------------------------------
// Fused GEMM kernel (v2: 256 threads, 2 warps/SMSP for latency hiding):
//   h  = relu(BN(mean@W1l^T + b1l + x@W1r^T))        (smem only)
//   hl = h @ W2l^T            -> g_hl
//   ho = h @ W2r^T + b2l      -> g_ho
// Weights in smem (192 KB) + 8 warps * 4 KB node buffers = 224 KB.
// 4 nodes per warp-task; f32x2 packed FMAs; lane owns 4 output channels.
// ---------------------------------------------------------------------------
__global__ __launch_bounds__(256, 1)
void fused_kernel(const float* __restrict__ x,
                  const float* __restrict__ W1l,
                  const float* __restrict__ b1l,
                  const float* __restrict__ W1r,
                  const float* __restrict__ gamma,
                  const float* __restrict__ beta,
                  const float* __restrict__ rmean,
                  const float* __restrict__ rvar,
                  const float* __restrict__ W2l,
                  const float* __restrict__ b2l,
                  const float* __restrict__ W2r) {
    extern __shared__ float sm[];
    float* WTl = sm;             // 16384 floats
    float* WTr = sm + 16384;     // 16384
    float* W2c = sm + 32768;     // 16384
    float* buf = sm + 49152;     // 8 warps * 1024 floats

    for (int i = threadIdx.x; i < 16384; i += blockDim.x) {
        int k = i >> 7, j = i & 127;
        WTl[i] = W1l[j * 128 + k];
        WTr[i] = W1r[j * 128 + k];
        W2c[i] = (j < 64) ? W2l[j * 128 + k] : W2r[(j - 64) * 128 + k];
    }
    __syncthreads();

    int wid = threadIdx.x >> 5, lane = threadIdx.x & 31;
    float* mb = buf + wid * 1024;   // [4][128]  (mean, later h)
    float* xb = mb + 512;           // [4][128]  (x)

    // BN constants for lane's 4 channels c = 4*lane .. 4*lane+3
    float4 g4  = ((const float4*)gamma)[lane];
    float4 be4 = ((const float4*)beta)[lane];
    float4 rm4 = ((const float4*)rmean)[lane];
    float4 rv4 = ((const float4*)rvar)[lane];
    float4 bl4 = ((const float4*)b1l)[lane];
    float sx = g4.x * rsqrtf(rv4.x + 1e-5f);
    float sy = g4.y * rsqrtf(rv4.y + 1e-5f);
    float sz = g4.z * rsqrtf(rv4.z + 1e-5f);
    float sw = g4.w * rsqrtf(rv4.w + 1e-5f);
    u64 sc01 = pack2(sx, sy), sc23 = pack2(sz, sw);
    u64 sh01 = pack2((bl4.x - rm4.x) * sx + be4.x, (bl4.y - rm4.y) * sy + be4.y);
    u64 sh23 = pack2((bl4.z - rm4.z) * sz + be4.z, (bl4.w - rm4.w) * sw + be4.w);

    float4 b2v = make_float4(0.f, 0.f, 0.f, 0.f);
    if (lane >= 16) b2v = ((const float4*)b2l)[lane - 16];

    int gw = blockIdx.x * 8 + wid;
    int nw = gridDim.x * 8;
    const int NTASK = NN / 4;   // 25000

    for (int t = gw; t < NTASK; t += nw) {
        int base = t * 4;
        // ---- stage x rows and mean rows into per-warp smem ----
        #pragma unroll
        for (int m = 0; m < 4; m++) {
            int node = base + m;
            ((float4*)(xb + m * 128))[lane] =
                ((const float4*)(x + (size_t)node * 128))[lane];
            float inv = 1.0f / fmaxf(g_cnt[node], 1.0f);
            float4 a = ((const float4*)(g_agg1 + (size_t)node * 128))[lane];
            a.x *= inv; a.y *= inv; a.z *= inv; a.w *= inv;
            ((float4*)(mb + m * 128))[lane] = a;
        }
        __syncwarp();

        // ---- phase 1: acc = mean@W1l^T + x@W1r^T ----
        u64 acc0[4], acc1[4];
        #pragma unroll
        for (int m = 0; m < 4; m++) { acc0[m] = 0ull; acc1[m] = 0ull; }

        for (int k0 = 0; k0 < 128; k0 += 4) {
            float4 s[4];
            // pass A: mean * W1l
            #pragma unroll
            for (int m = 0; m < 4; m++) s[m] = *(const float4*)(mb + m * 128 + k0);
            #pragma unroll
            for (int kk = 0; kk < 4; kk++) {
                ulonglong2 w = ((const ulonglong2*)(WTl + (k0 + kk) * 128))[lane];
                #pragma unroll
                for (int m = 0; m < 4; m++) {
                    float v = (kk == 0) ? s[m].x : (kk == 1) ? s[m].y
                             : (kk == 2) ? s[m].z : s[m].w;
                    u64 d = dup2(v);
                    acc0[m] = fma2(d, w.x, acc0[m]);
                    acc1[m] = fma2(d, w.y, acc1[m]);
                }
            }
            // pass B: x * W1r
            #pragma unroll
            for (int m = 0; m < 4; m++) s[m] = *(const float4*)(xb + m * 128 + k0);
            #pragma unroll
            for (int kk = 0; kk < 4; kk++) {
                ulonglong2 w = ((const ulonglong2*)(WTr + (k0 + kk) * 128))[lane];
                #pragma unroll
                for (int m = 0; m < 4; m++) {
                    float v = (kk == 0) ? s[m].x : (kk == 1) ? s[m].y
                             : (kk == 2) ? s[m].z : s[m].w;
                    u64 d = dup2(v);
                    acc0[m] = fma2(d, w.x, acc0[m]);
                    acc1[m] = fma2(d, w.y, acc1[m]);
                }
            }
        }

        // ---- epilogue 1: BN + ReLU, write h into mb ----
        __syncwarp();
        #pragma unroll
        for (int m = 0; m < 4; m++) {
            u64 h01 = fma2(acc0[m], sc01, sh01);
            u64 h23 = fma2(acc1[m], sc23, sh23);
            float2 a = unpack2(h01), b = unpack2(h23);
            float4 h4;
            h4.x = fmaxf(a.x, 0.f); h4.y = fmaxf(a.y, 0.f);
            h4.z = fmaxf(b.x, 0.f); h4.w = fmaxf(b.y, 0.f);
            ((float4*)(mb + m * 128))[lane] = h4;
        }
        __syncwarp();

        // ---- phase 2: [hl|ho] = h @ W2c ----
        u64 p0[4], p1[4];
        #pragma unroll
        for (int m = 0; m < 4; m++) { p0[m] = 0ull; p1[m] = 0ull; }

        for (int k0 = 0; k0 < 128; k0 += 4) {
            float4 s[4];
            #pragma unroll
            for (int m = 0; m < 4; m++) s[m] = *(const float4*)(mb + m * 128 + k0);
            #pragma unroll
            for (int kk = 0; kk < 4; kk++) {
                ulonglong2 w = ((const ulonglong2*)(W2c + (k0 + kk) * 128))[lane];
                #pragma unroll
                for (int m = 0; m < 4; m++) {
                    float v = (kk == 0) ? s[m].x : (kk == 1) ? s[m].y
                             : (kk == 2) ? s[m].z : s[m].w;
                    u64 d = dup2(v);
                    p0[m] = fma2(d, w.x, p0[m]);
                    p1[m] = fma2(d, w.y, p1[m]);
                }
            }
        }

        // ---- epilogue 2: lanes 0-15 -> hl, lanes 16-31 -> ho (+b2) ----
        #pragma unroll
        for (int m = 0; m < 4; m++) {
            float2 a = unpack2(p0[m]), b = unpack2(p1[m]);
            int node = base + m;
            if (lane < 16) {
                float4 v = make_float4(a.x, a.y, b.x, b.y);
                ((float4*)(g_hl + (size_t)node * 64))[lane] = v;
            } else {
                float4 v = make_float4(a.x + b2v.x, a.y + b2v.y,
                                       b.x + b2v.z, b.y + b2v.w);
                ((float4*)(g_ho + (size_t)node * 64))[lane - 16] = v;
            }
        }
        __syncwarp();
    }
}

// ---------------------------------------------------------------------------
// out = ho + agg2 / cnt   (elementwise, float4 granularity)
// ---------------------------------------------------------------------------
__global__ void out_add_kernel(float* __restrict__ out) {
    int tid = blockIdx.x * blockDim.x + threadIdx.x;
    int stride = gridDim.x * blockDim.x;
    const float4* ho4 = (const float4*)g_ho;
    const float4* a4  = (const float4*)g_agg2;
    float4* o4 = (float4*)out;
    for (int i = tid; i < NN * 16; i += stride) {   // 16 float4 per node row
        int node = i >> 4;
        float inv = 1.0f / fmaxf(g_cnt[node], 1.0f);
        float4 h = ho4[i];
        float4 a = a4[i];
        h.x += a.x * inv; h.y += a.y * inv;
        h.z += a.z * inv; h.w += a.w * inv;
        o4[i] = h;
    }
}

// ---------------------------------------------------------------------------
extern "C" void kernel_launch(void* const* d_in, const int* in_sizes, int n_in,
                              void* d_out, int out_size) {
    const float* x     = (const float*)d_in[0];
    const int*   ei    = (const int*)d_in[1];
    const float* W1l   = (const float*)d_in[2];
    const float* b1l   = (const float*)d_in[3];
    const float* W1r   = (const float*)d_in[4];
    const float* gamma = (const float*)d_in[5];
    const float* beta  = (const float*)d_in[6];
    const float* rmean = (const float*)d_in[7];
    const float* rvar  = (const float*)d_in[8];
    const float* W2l   = (const float*)d_in[9];
    const float* b2l   = (const float*)d_in[10];
    const float* W2r   = (const float*)d_in[11];
    float* out = (float*)d_out;

    const int SMEMF = (49152 + 8 * 1024) * 4;   // 229376 B
    cudaFuncSetAttribute(fused_kernel, cudaFuncAttributeMaxDynamicSharedMemorySize, SMEMF);

    zero_kernel<<<1024, 256>>>();
    scatter1_kernel<<<8192, 256>>>(x, ei);
    fused_kernel<<<152, 256, SMEMF>>>(x, W1l, b1l, W1r, gamma, beta, rmean,
                                      rvar, W2l, b2l, W2r);
    scatter2_kernel<<<8192, 256>>>(ei);
    out_add_kernel<<<2048, 256>>>(out);
}